// round 3
// baseline (speedup 1.0000x reference)
#include <cuda_runtime.h>

#define BB 16
#define QQ 300
#define SNUM 16
#define HID 256
#define T_TOT 13125
#define W0 100
#define H0 100
#define QP 3
#define S_SCALE_C 0.077f
#define RB 6                      // rows per block in kernel 1
#define NBLK1 (BB * QP * SNUM / RB)   // 128

// scratch: pre-scaled tanh offsets for the 768 distinct (b, q', s) rows, 4 values each
__device__ float g_off[BB * QP * SNUM * 4];

typedef unsigned long long ull;

__device__ __forceinline__ ull pack2(float lo, float hi) {
    ull r;
    asm("mov.b64 %0, {%1, %2};" : "=l"(r) : "f"(lo), "f"(hi));
    return r;
}
__device__ __forceinline__ void unpack2(ull v, float& lo, float& hi) {
    asm("mov.b64 {%0, %1}, %2;" : "=f"(lo), "=f"(hi) : "l"(v));
}
__device__ __forceinline__ void fma2(ull& d, ull a, ull b) {
    asm("fma.rn.f32x2 %0, %1, %2, %3;" : "=l"(d) : "l"(a), "l"(b), "l"(d));
}

// Kernel 1: 6 rows per block. Bilinear sample level-0 features, 2-layer MLP head.
__global__ __launch_bounds__(HID) void sample_mlp_kernel(
        const float* __restrict__ rp,
        const float* __restrict__ mem,
        const float* __restrict__ w1,
        const float* __restrict__ b1,
        const float* __restrict__ w2,
        const float* __restrict__ b2) {
    const int blk = blockIdx.x;
    const int tid = threadIdx.x;                 // output / feature channel 0..255

    // gs[c*RB + r] : sampled feature, row-pairs contiguous for f32x2 loads
    __shared__ __align__(16) float gs[HID * RB];
    __shared__ float h1s[RB * HID];

    // ---- bilinear gather: thread tid gathers channel tid for each of RB rows ----
    #pragma unroll
    for (int r = 0; r < RB; r++) {
        const int row = blk * RB + r;            // b*48 + qp*16 + s
        const int s  = row & 15;
        const int qp = (row >> 4) % QP;
        const int b  = row / (QP * SNUM);

        const float* rpq = rp + ((size_t)b * QQ + qp) * 8;
        const float t  = (float)s * (1.0f / (float)(SNUM - 1));
        const float t2 = t * t, t3 = t2 * t;
        const float gx = 2.0f * (rpq[0] * t3 + rpq[1] * t2 + rpq[2] * t + rpq[3] - 0.5f);
        const float gy = 2.0f * (rpq[4] * t3 + rpq[5] * t2 + rpq[6] * t + rpq[7] - 0.5f);
        const float x = (gx + 1.0f) * (W0 * 0.5f) - 0.5f;
        const float y = (gy + 1.0f) * (H0 * 0.5f) - 0.5f;
        const float x0f = floorf(x), y0f = floorf(y);
        const int x0 = (int)x0f, y0 = (int)y0f;
        const float wx1 = x - x0f, wx0 = 1.0f - wx1;
        const float wy1 = y - y0f, wy0 = 1.0f - wy1;

        const float* memb = mem + (size_t)b * T_TOT * HID;
        float acc = 0.0f;
        #pragma unroll
        for (int dy = 0; dy < 2; dy++) {
            const int yi = y0 + dy;
            const float wy = dy ? wy1 : wy0;
            if (yi < 0 || yi >= H0) continue;
            #pragma unroll
            for (int dx = 0; dx < 2; dx++) {
                const int xi = x0 + dx;
                const float wx = dx ? wx1 : wx0;
                if (xi < 0 || xi >= W0) continue;
                acc += wy * wx * __ldg(&memb[(size_t)(yi * W0 + xi) * HID + tid]);
            }
        }
        gs[tid * RB + r] = acc;
    }
    __syncthreads();

    // ---- layer 1: h1[r][tid] = tanh(b1[tid] + sum_c gs[r][c] * w1[c][tid]) ----
    // 3 f32x2 accumulators = 6 rows packed pairwise.
    const float bv = b1[tid];
    ull acc0 = pack2(bv, bv), acc1 = pack2(bv, bv), acc2 = pack2(bv, bv);
    const float* w1c = w1 + tid;
    #pragma unroll 8
    for (int c = 0; c < HID; c++) {
        const float w = __ldg(w1c + c * HID);
        const ull wp = pack2(w, w);
        const ull g0 = *reinterpret_cast<const ull*>(&gs[c * RB + 0]);
        const ull g1 = *reinterpret_cast<const ull*>(&gs[c * RB + 2]);
        const ull g2 = *reinterpret_cast<const ull*>(&gs[c * RB + 4]);
        fma2(acc0, g0, wp);
        fma2(acc1, g1, wp);
        fma2(acc2, g2, wp);
    }
    {
        float a, b;
        unpack2(acc0, a, b);
        h1s[0 * HID + tid] = tanhf(a); h1s[1 * HID + tid] = tanhf(b);
        unpack2(acc1, a, b);
        h1s[2 * HID + tid] = tanhf(a); h1s[3 * HID + tid] = tanhf(b);
        unpack2(acc2, a, b);
        h1s[4 * HID + tid] = tanhf(a); h1s[5 * HID + tid] = tanhf(b);
    }
    __syncthreads();

    // ---- layer 2: 24 dot products (6 rows x 4 outputs), 3 per warp ----
    const int wid = tid >> 5, lane = tid & 31;
    #pragma unroll
    for (int d = wid * 3; d < wid * 3 + 3; d++) {
        const int r = d >> 2, k = d & 3;
        float a2 = 0.0f;
        #pragma unroll
        for (int j = lane; j < HID; j += 32)
            a2 += h1s[r * HID + j] * w2[j * 4 + k];
        #pragma unroll
        for (int o = 16; o > 0; o >>= 1)
            a2 += __shfl_xor_sync(0xffffffffu, a2, o);
        if (lane == 0)
            g_off[(blk * RB + r) * 4 + k] = S_SCALE_C * tanhf(a2 + b2[k]);
    }
}

// Kernel 2: block = (b, group of 16 q). Stage g_off slice + rp + rl in smem, write float4.
#define QG 16
#define NQG ((QQ + QG - 1) / QG)   // 19
__global__ __launch_bounds__(256) void out_kernel(
        const float* __restrict__ rp,
        const int* __restrict__ rl,
        float* __restrict__ out) {
    const int b  = blockIdx.x / NQG;
    const int qg = blockIdx.x % NQG;
    const int q0 = qg * QG;
    const int tid = threadIdx.x;

    __shared__ float offs[QP * SNUM * 4];   // 192: this b's g_off slice
    __shared__ float rps[QG * 8];           // 128: rp coefs for the 16 q's
    __shared__ int   rls[QG];

    if (tid < QP * SNUM * 4)
        offs[tid] = g_off[b * (QP * SNUM * 4) + tid];
    if (tid < QG * 8) {
        const int qq = q0 + (tid >> 3);
        rps[tid] = (qq < QQ) ? rp[((size_t)b * QQ + q0) * 8 + tid] : 0.0f;
    }
    if (tid < QG) {
        const int qq = q0 + tid;
        rls[tid] = (qq < QQ) ? rl[b * QQ + qq] : 0;
    }
    __syncthreads();

    const int ql = tid >> 4;        // 0..15
    const int s  = tid & 15;
    const int q  = q0 + ql;
    if (q >= QQ) return;

    const float* c = &rps[ql * 8];
    const float t  = (float)s * (1.0f / (float)(SNUM - 1));
    const float t2 = t * t, t3 = t2 * t;
    const float spx = 2.0f * (c[0] * t3 + c[1] * t2 + c[2] * t + c[3] - 0.5f);
    const float spy = 2.0f * (c[4] * t3 + c[5] * t2 + c[6] * t + c[7] - 0.5f);

    const float* o = &offs[(rls[ql] * SNUM + s) * 4];
    float4 v;
    v.x = o[0] + spx;
    v.y = o[1] + spy;
    v.z = o[2] + spx;
    v.w = o[3] + spy;
    reinterpret_cast<float4*>(out)[((size_t)b * QQ + q) * SNUM + s] = v;
}

extern "C" void kernel_launch(void* const* d_in, const int* in_sizes, int n_in,
                              void* d_out, int out_size) {
    const float* ref_polys = (const float*)d_in[0];
    const float* memory    = (const float*)d_in[1];
    const float* w1        = (const float*)d_in[2];
    const float* b1        = (const float*)d_in[3];
    const float* w2        = (const float*)d_in[4];
    const float* b2        = (const float*)d_in[5];
    const int*   ref_lvls  = (const int*)d_in[6];
    float* out = (float*)d_out;

    sample_mlp_kernel<<<NBLK1, HID>>>(ref_polys, memory, w1, b1, w2, b2);
    out_kernel<<<BB * NQG, 256>>>(ref_polys, ref_lvls, out);
}

// round 4
// speedup vs baseline: 1.1175x; 1.1175x over previous
#include <cuda_runtime.h>

#define BB 16
#define QQ 300
#define SNUM 16
#define HID 256
#define T_TOT 13125
#define W0 100
#define H0 100
#define QP 3
#define S_SCALE_C 0.077f
#define NBLK 192
#define RB 4
#define ITEMS (BB * QQ * SNUM)      // 76800
#define PER_BLK (ITEMS / NBLK)      // 400

__device__ __align__(16) float g_off[BB * QP * SNUM * 4];
__device__ unsigned g_cnt;          // cumulative across launches, never reset

typedef unsigned long long ull;

__device__ __forceinline__ ull pack2(float lo, float hi) {
    ull r; asm("mov.b64 %0, {%1, %2};" : "=l"(r) : "f"(lo), "f"(hi)); return r;
}
__device__ __forceinline__ void unpack2(ull v, float& lo, float& hi) {
    asm("mov.b64 {%0, %1}, %2;" : "=f"(lo), "=f"(hi) : "l"(v));
}
__device__ __forceinline__ void fma2(ull& d, ull a, ull b) {
    asm("fma.rn.f32x2 %0, %1, %2, %3;" : "=l"(d) : "l"(a), "l"(b), "l"(d));
}
__device__ __forceinline__ float tanh_fast(float x) {
    float r; asm("tanh.approx.f32 %0, %1;" : "=f"(r) : "f"(x)); return r;
}
__device__ __forceinline__ unsigned ld_cg_u32(const unsigned* p) {
    unsigned v; asm volatile("ld.global.cg.u32 %0, [%1];" : "=r"(v) : "l"(p)); return v;
}

__device__ __forceinline__ void poly_xy(const float* __restrict__ c, int s,
                                        float& spx, float& spy) {
    const float t  = (float)s * (1.0f / (float)(SNUM - 1));
    const float t2 = t * t, t3 = t2 * t;
    spx = 2.0f * (c[0] * t3 + c[1] * t2 + c[2] * t + c[3] - 0.5f);
    spy = 2.0f * (c[4] * t3 + c[5] * t2 + c[6] * t + c[7] - 0.5f);
}

__global__ __launch_bounds__(256, 2) void fused_kernel(
        const float* __restrict__ rp,
        const float* __restrict__ mem,
        const float* __restrict__ w1,
        const float* __restrict__ b1,
        const float* __restrict__ w2,
        const float* __restrict__ b2,
        const int* __restrict__ rl,
        float* __restrict__ out) {
    const int blk = blockIdx.x;
    const int tid = threadIdx.x;

    __shared__ float gs2[RB * HID];                       // [r][c] gathered features
    __shared__ __align__(16) float gsp[HID * RB];         // [c][r] packed for f32x2
    __shared__ float h1s[RB * HID];
    __shared__ unsigned sh_target;

    // ================= Phase A: 4 rows (b, q'<3, s) -> g_off =================
    {
        // 64 threads per row, each thread gathers 4 channels via float4
        const int r   = tid >> 6;            // 0..3
        const int u   = tid & 63;            // channel group (4 ch each)
        const int row = blk * RB + r;        // b*48 + qp*16 + s
        const int s   = row & 15;
        const int qp  = (row >> 4) % QP;
        const int b   = row / (QP * SNUM);

        float gx, gy;
        poly_xy(rp + ((size_t)b * QQ + qp) * 8, s, gx, gy);
        const float x = (gx + 1.0f) * (W0 * 0.5f) - 0.5f;
        const float y = (gy + 1.0f) * (H0 * 0.5f) - 0.5f;
        const float x0f = floorf(x), y0f = floorf(y);
        const int x0 = (int)x0f, y0 = (int)y0f;
        const float wx1 = x - x0f, wx0 = 1.0f - wx1;
        const float wy1 = y - y0f, wy0 = 1.0f - wy1;

        const float* memb = mem + (size_t)b * T_TOT * HID;
        float4 acc = make_float4(0.f, 0.f, 0.f, 0.f);
        #pragma unroll
        for (int dy = 0; dy < 2; dy++) {
            const int yi = y0 + dy;
            if (yi < 0 || yi >= H0) continue;
            const float wy = dy ? wy1 : wy0;
            #pragma unroll
            for (int dx = 0; dx < 2; dx++) {
                const int xi = x0 + dx;
                if (xi < 0 || xi >= W0) continue;
                const float wgt = wy * (dx ? wx1 : wx0);
                const float4 v = __ldg(reinterpret_cast<const float4*>(
                    memb + (size_t)(yi * W0 + xi) * HID + u * 4));
                acc.x += wgt * v.x; acc.y += wgt * v.y;
                acc.z += wgt * v.z; acc.w += wgt * v.w;
            }
        }
        *reinterpret_cast<float4*>(&gs2[r * HID + u * 4]) = acc;
    }
    __syncthreads();

    // transpose [r][c] -> packed [c][r] (conflict-free both sides)
    {
        float4 p;
        p.x = gs2[0 * HID + tid]; p.y = gs2[1 * HID + tid];
        p.z = gs2[2 * HID + tid]; p.w = gs2[3 * HID + tid];
        *reinterpret_cast<float4*>(&gsp[tid * 4]) = p;
    }
    __syncthreads();

    // layer 1: thread = output channel, 2 f32x2 accumulators = 4 rows
    {
        const float bv = b1[tid];
        ull a0 = pack2(bv, bv), a1 = pack2(bv, bv);
        const float* w1c = w1 + tid;
        #pragma unroll 8
        for (int c = 0; c < HID; c++) {
            const float w = __ldg(w1c + c * HID);
            const ull wp = pack2(w, w);
            const ull gA = *reinterpret_cast<const ull*>(&gsp[c * 4 + 0]);
            const ull gB = *reinterpret_cast<const ull*>(&gsp[c * 4 + 2]);
            fma2(a0, gA, wp);
            fma2(a1, gB, wp);
        }
        float v0, v1;
        unpack2(a0, v0, v1);
        h1s[0 * HID + tid] = tanh_fast(v0);
        h1s[1 * HID + tid] = tanh_fast(v1);
        unpack2(a1, v0, v1);
        h1s[2 * HID + tid] = tanh_fast(v0);
        h1s[3 * HID + tid] = tanh_fast(v1);
    }
    __syncthreads();

    // layer 2: 16 dots (4 rows x 4 outs), 2 per warp
    {
        const int wid = tid >> 5, lane = tid & 31;
        #pragma unroll
        for (int d = wid * 2; d < wid * 2 + 2; d++) {
            const int r = d >> 2, k = d & 3;
            float a = 0.0f;
            #pragma unroll
            for (int j = lane; j < HID; j += 32)
                a += h1s[r * HID + j] * __ldg(&w2[j * 4 + k]);
            #pragma unroll
            for (int o = 16; o > 0; o >>= 1)
                a += __shfl_xor_sync(0xffffffffu, a, o);
            if (lane == 0)
                g_off[(blk * RB + r) * 4 + k] = S_SCALE_C * tanh_fast(a + b2[k]);
        }
    }

    // release: make g_off visible, then arrive
    __threadfence();
    __syncthreads();
    if (tid == 0) {
        const unsigned t = atomicAdd(&g_cnt, 1u);
        sh_target = t - (t % NBLK) + NBLK;   // all tickets this launch share one epoch
    }

    // ================= Phase B prologue (independent of g_off) ===============
    float spx[2], spy[2];
    int lvl[2];
    int bI[2], sI[2], idxI[2];
    bool valid[2];
    #pragma unroll
    for (int p = 0; p < 2; p++) {
        const int idx = blk * PER_BLK + p * 256 + tid;
        valid[p] = (p == 0) || (tid < PER_BLK - 256);
        idxI[p] = idx;
        if (valid[p]) {
            const int s  = idx & 15;
            const int qb = idx >> 4;
            const int q  = qb % QQ;
            const int b  = qb / QQ;
            poly_xy(rp + ((size_t)b * QQ + q) * 8, s, spx[p], spy[p]);
            lvl[p] = rl[b * QQ + q];
            bI[p] = b; sI[p] = s;
        }
    }

    // ================= barrier: wait for all 192 blocks ======================
    __syncthreads();                         // sh_target visible to thread 0 path
    if (tid == 0) {
        const unsigned tgt = sh_target;
        while ((int)(ld_cg_u32(&g_cnt) - tgt) < 0)
            __nanosleep(64);
    }
    __syncthreads();
    __threadfence();                         // acquire

    // ================= Phase B epilogue: gather offsets, write ===============
    #pragma unroll
    for (int p = 0; p < 2; p++) {
        if (!valid[p]) continue;
        const float* o = g_off + (((size_t)bI[p] * QP + lvl[p]) * SNUM + sI[p]) * 4;
        const float4 ov = __ldcg(reinterpret_cast<const float4*>(o));
        float4 v;
        v.x = ov.x + spx[p];
        v.y = ov.y + spy[p];
        v.z = ov.z + spx[p];
        v.w = ov.w + spy[p];
        reinterpret_cast<float4*>(out)[idxI[p]] = v;
    }
}

extern "C" void kernel_launch(void* const* d_in, const int* in_sizes, int n_in,
                              void* d_out, int out_size) {
    const float* ref_polys = (const float*)d_in[0];
    const float* memory    = (const float*)d_in[1];
    const float* w1        = (const float*)d_in[2];
    const float* b1        = (const float*)d_in[3];
    const float* w2        = (const float*)d_in[4];
    const float* b2        = (const float*)d_in[5];
    const int*   ref_lvls  = (const int*)d_in[6];
    float* out = (float*)d_out;

    fused_kernel<<<NBLK, 256>>>(ref_polys, memory, w1, b1, w2, b2, ref_lvls, out);
}